// round 6
// baseline (speedup 1.0000x reference)
#include <cuda_runtime.h>

#define N_NODES 50000
#define N_EDGES 800000
#define NFEAT   256
#define NCLASS  64
#define CAP     80          // per-node padded in-degree capacity (Poisson(16); P(>80)~1e-30)

typedef unsigned long long ull;

// ---------------- scratch (no allocations allowed) ----------------
__device__ int   g_cur [N_NODES];           // fill cursors; == in-degree after fill
__device__ float g_dinv[N_NODES];
__device__ int   g_srci[N_NODES * CAP];     // staged src per slot
__device__ ull   g_rec [N_NODES * CAP];     // packed {w (hi 32), src (lo 32)}
__device__ float g_buf0[N_NODES * NCLASS];
__device__ float g_buf1[N_NODES * NCLASS];

// ---------------- streams/events for fork-join capture ----------------
static cudaStream_t g_s1;
static cudaEvent_t  g_evFork, g_evJoin;
static struct SideInit {
    SideInit() {
        cudaStreamCreateWithFlags(&g_s1, cudaStreamNonBlocking);
        cudaEventCreateWithFlags(&g_evFork, cudaEventDisableTiming);
        cudaEventCreateWithFlags(&g_evJoin, cudaEventDisableTiming);
    }
} g_sideInit;

// ---------------- f32x2 packed helpers ----------------
__device__ __forceinline__ ull pack2(float x, float y) {
    ull d;
    asm("mov.b64 %0, {%1, %2};" : "=l"(d) : "f"(x), "f"(y));
    return d;
}
__device__ __forceinline__ ull fma2(ull a, ull b, ull c) {
    ull d;
    asm("fma.rn.f32x2 %0, %1, %2, %3;" : "=l"(d) : "l"(a), "l"(b), "l"(c));
    return d;
}
__device__ __forceinline__ void unpack2(ull d, float& x, float& y) {
    asm("mov.b64 {%0, %1}, %2;" : "=f"(x), "=f"(y) : "l"(d));
}

// ---------------- padded-CSR build (no scan needed) ----------------
__global__ void fill_kernel(const int* __restrict__ ei) {
    int e = blockIdx.x * blockDim.x + threadIdx.x;
    if (e < N_EDGES) {
        unsigned s = (unsigned)ei[e];
        unsigned d = (unsigned)ei[N_EDGES + e];
        if (s < N_NODES && d < N_NODES) {
            int pos = atomicAdd(&g_cur[d], 1);
            if (pos < CAP) g_srci[d * CAP + pos] = (int)s;
        }
    }
}

__global__ void dinv_kernel() {
    int i = blockIdx.x * blockDim.x + threadIdx.x;
    if (i < N_NODES) g_dinv[i] = rsqrtf((float)(g_cur[i] + 1));   // +1 self loop
}

// warp per node: pack (w, src) records
__global__ void pack_kernel() {
    int gtid = blockIdx.x * blockDim.x + threadIdx.x;
    int node = gtid >> 5;
    int lane = threadIdx.x & 31;
    if (node >= N_NODES) return;
    int deg = g_cur[node];
    if (deg > CAP) deg = CAP;
    float dd = g_dinv[node];
    int base = node * CAP;
    for (int j = lane; j < deg; j += 32) {
        int s = g_srci[base + j];
        float w = g_dinv[s] * dd;
        g_rec[base + j] = ((ull)__float_as_uint(w) << 32) | (ull)(unsigned)s;
    }
}

// ---------------- GEMM: Y0[50000,64] = x[50000,256] @ W[256,64] (f32x2 packed) ----------------
__global__ void gemm_kernel(const float* __restrict__ x,
                            const float* __restrict__ W,
                            float* __restrict__ y) {
    __shared__ float xs[64][36];   // [row][k], padded for float4 stores
    __shared__ ull   ws2[32][34];  // [k][col-pair], 16B-aligned rows

    int t  = threadIdx.x;
    int tx = t & 15;               // col group (cols tx*4 .. tx*4+3)
    int ty = t >> 4;               // row group (rows ty*4 .. ty*4+3)
    int row0 = blockIdx.x * 64;

    ull acc[4][2];
#pragma unroll
    for (int r = 0; r < 4; r++) { acc[r][0] = 0ULL; acc[r][1] = 0ULL; }

    for (int k0 = 0; k0 < NFEAT; k0 += 32) {
#pragma unroll
        for (int i = 0; i < 2; i++) {
            int idx = t + i * 256;
            int r   = idx >> 3;
            int kq  = idx & 7;
            int row = row0 + r;
            float4 v = make_float4(0.f, 0.f, 0.f, 0.f);
            if (row < N_NODES)
                v = *(const float4*)&x[row * NFEAT + k0 + kq * 4];
            *(float4*)&xs[r][kq * 4] = v;
        }
#pragma unroll
        for (int i = 0; i < 2; i++) {
            int idx = t + i * 256;
            int kk  = idx >> 4;
            int cq  = idx & 15;
            float4 v = *(const float4*)&W[(k0 + kk) * NCLASS + cq * 4];
            ws2[kk][cq * 2 + 0] = pack2(v.x, v.y);
            ws2[kk][cq * 2 + 1] = pack2(v.z, v.w);
        }
        __syncthreads();

#pragma unroll
        for (int kk = 0; kk < 32; kk++) {
            ulonglong2 b = *(const ulonglong2*)&ws2[kk][tx * 2];
#pragma unroll
            for (int r = 0; r < 4; r++) {
                float a = xs[ty * 4 + r][kk];
                ull ap = pack2(a, a);
                acc[r][0] = fma2(ap, b.x, acc[r][0]);
                acc[r][1] = fma2(ap, b.y, acc[r][1]);
            }
        }
        __syncthreads();
    }

#pragma unroll
    for (int r = 0; r < 4; r++) {
        int row = row0 + ty * 4 + r;
        if (row < N_NODES) {
            float4 o;
            unpack2(acc[r][0], o.x, o.y);
            unpack2(acc[r][1], o.z, o.w);
            *(float4*)&y[row * NCLASS + tx * 4] = o;
        }
    }
}

// ---------------- pull-based hop (warp per node, float2 per lane) ----------------
// y[i] = dinv_i^2 * x[i] + sum_{e: dst=i} w_e * x[src_e]  (+ bias)
__global__ void hop_kernel(const float* __restrict__ xin,
                           float* __restrict__ yout,
                           const float* __restrict__ bias) {
    int gtid = blockIdx.x * blockDim.x + threadIdx.x;
    int node = gtid >> 5;
    int lane = threadIdx.x & 31;
    if (node >= N_NODES) return;

    int deg = g_cur[node];
    if (deg > CAP) deg = CAP;
    const ull* rec = g_rec + node * CAP;   // 640B-aligned base -> LDG.128 ok
    float di = g_dinv[node];
    float w0 = di * di;

    ull v = *(const ull*)(xin + node * NCLASS + lane * 2);
    ull base = bias ? *(const ull*)(bias + lane * 2) : 0ULL;
    ull acc = fma2(pack2(w0, w0), v, base);

    int j = 0;
    for (; j + 4 <= deg; j += 4) {
        ulonglong2 ra = *(const ulonglong2*)(rec + j);
        ulonglong2 rb = *(const ulonglong2*)(rec + j + 2);
        int s0 = (int)(unsigned)ra.x;  float wa = __uint_as_float((unsigned)(ra.x >> 32));
        int s1 = (int)(unsigned)ra.y;  float wb = __uint_as_float((unsigned)(ra.y >> 32));
        int s2 = (int)(unsigned)rb.x;  float wc = __uint_as_float((unsigned)(rb.x >> 32));
        int s3 = (int)(unsigned)rb.y;  float wd = __uint_as_float((unsigned)(rb.y >> 32));
        ull u0 = *(const ull*)(xin + s0 * NCLASS + lane * 2);
        ull u1 = *(const ull*)(xin + s1 * NCLASS + lane * 2);
        ull u2 = *(const ull*)(xin + s2 * NCLASS + lane * 2);
        ull u3 = *(const ull*)(xin + s3 * NCLASS + lane * 2);
        acc = fma2(pack2(wa, wa), u0, acc);
        acc = fma2(pack2(wb, wb), u1, acc);
        acc = fma2(pack2(wc, wc), u2, acc);
        acc = fma2(pack2(wd, wd), u3, acc);
    }
    for (; j < deg; j++) {
        ull r0 = rec[j];
        int   s0 = (int)(unsigned)r0;
        float wa = __uint_as_float((unsigned)(r0 >> 32));
        ull u0 = *(const ull*)(xin + s0 * NCLASS + lane * 2);
        acc = fma2(pack2(wa, wa), u0, acc);
    }

    *(ull*)(yout + node * NCLASS + lane * 2) = acc;
}

// ---------------- launch ----------------
extern "C" void kernel_launch(void* const* d_in, const int* in_sizes, int n_in,
                              void* d_out, int out_size) {
    const float* x  = (const float*)d_in[0];
    const int*   ei = (const int*)d_in[1];
    const float* W  = (const float*)d_in[2];
    const float* b  = (const float*)d_in[3];
    float* out = (float*)d_out;

    float *buf0, *buf1;
    cudaGetSymbolAddress((void**)&buf0, g_buf0);
    cudaGetSymbolAddress((void**)&buf1, g_buf1);
    int* cur_ptr;
    cudaGetSymbolAddress((void**)&cur_ptr, g_cur);

    const int T = 256;
    int gE = (N_EDGES + T - 1) / T;
    int gN = (N_NODES + T - 1) / T;
    int gW = (N_NODES * 32 + T - 1) / T;      // warp per node
    int gG = (N_NODES + 63) / 64;             // gemm blocks

    // Fork: GEMM (x, W only) on side stream, concurrent with CSR build (edge_index only).
    cudaEventRecord(g_evFork, 0);
    cudaStreamWaitEvent(g_s1, g_evFork, 0);
    gemm_kernel<<<gG, T, 0, g_s1>>>(x, W, buf0);
    cudaEventRecord(g_evJoin, g_s1);

    // Padded-CSR build on main stream (no histogram, no scan)
    cudaMemsetAsync(cur_ptr, 0, N_NODES * sizeof(int), 0);
    fill_kernel<<<gE, T>>>(ei);
    dinv_kernel<<<gN, T>>>();
    pack_kernel<<<gW, T>>>();

    // Join: hops need both buf0 (GEMM) and packed records
    cudaStreamWaitEvent(0, g_evJoin, 0);

    hop_kernel<<<gW, T>>>(buf0, buf1, nullptr);
    hop_kernel<<<gW, T>>>(buf1, buf0, nullptr);
    hop_kernel<<<gW, T>>>(buf0, out, b);
}